// round 15
// baseline (speedup 1.0000x reference)
#include <cuda_runtime.h>
#include <math.h>

// Problem constants
#define BB     256
#define TT     4096
#define NN     8
#define TWO_N  16
#define PP     144      // 2N + 2N^2
#define HH     64

// latent/dlatent base table over tt in [0,1): 328 segments, lerp err ~4e-6
#define TPTS   329
#define TSEG   328
#define ROWF   36       // base table row stride (floats)

// expanded smem row: s[16] | ur[8] | vr[8] | psi | pad3 = 36 floats
#define ROWB   36
#define ROWB4  9

// 2 blocks per batch row, 256 thr, 8 samples/thread (2 groups of 4 consecutive)
#define GRID_MAIN 512
#define BLK       256
#define SPT       8
#define GRP       (SPT / 4)      // groups of 4 consecutive samples

__device__ __align__(16) float g_table[TPTS * ROWF];     // latent|dlatent
__device__ double   g_partd[GRID_MAIN];
__device__ double   g_parts[GRID_MAIN];
__device__ unsigned g_cnt = 0;

// ---- packed f32x2 helpers ------------------------------------------------
typedef unsigned long long u64;
__device__ __forceinline__ u64 fma2(u64 a, u64 b, u64 c) {
    u64 d; asm("fma.rn.f32x2 %0, %1, %2, %3;" : "=l"(d) : "l"(a), "l"(b), "l"(c)); return d;
}
__device__ __forceinline__ u64 pack2(float lo, float hi) {
    u64 d; asm("mov.b64 %0, {%1, %2};" : "=l"(d) : "f"(lo), "f"(hi)); return d;
}
union F4 { float4 v; u64 u[2]; };

#define NEG1C 0xBF800000BF800000ULL   // {-1.0f, -1.0f}

// lerp: r = a0 + f*(a1-a0); diff via fma2(NEG1,a0,a1) -> only f2 needed
__device__ __forceinline__ float4 lerp4(const float4* base, int q, u64 f2) {
    F4 a0, a1, r;
    a0.v = base[q]; a1.v = base[q + ROWB4];
    r.u[0] = fma2(f2, fma2(NEG1C, a0.u[0], a1.u[0]), a0.u[0]);
    r.u[1] = fma2(f2, fma2(NEG1C, a0.u[1], a1.u[1]), a0.u[1]);
    return r.v;
}

// ---------------------------------------------------------------------------
// Kernel 1: latent/dlatent vs tt (4 points / 256-thread block)
// ---------------------------------------------------------------------------
__global__ void table_kernel(const float* __restrict__ W1, const float* __restrict__ b1,
                             const float* __restrict__ W2, const float* __restrict__ b2) {
    __shared__ float sW2[HH * TWO_N];
    __shared__ float sb2[TWO_N];
    __shared__ float sh[4][HH];
    __shared__ float sdh[4][HH];
    const int tid = threadIdx.x;
    const int sub = tid >> 6;
    const int k   = tid & 63;
    const int m   = blockIdx.x * 4 + sub;

    for (int i = tid; i < HH * TWO_N; i += BLK) sW2[i] = W2[i];
    if (tid < TWO_N) sb2[tid] = b2[tid];

    float tt = (float)m * (1.0f / (float)TSEG);
    float w  = W1[k];
    float h  = tanhf(fmaf(tt, w, b1[k]));
    sh[sub][k]  = h;
    sdh[sub][k] = (1.0f - h * h) * w;
    __syncthreads();

    if (k < TWO_N && m < TPTS) {
        float lat = sb2[k];
        float dl  = 0.0f;
#pragma unroll
        for (int j = 0; j < HH; j++) {
            float w2 = sW2[j * TWO_N + k];
            lat = fmaf(sh[sub][j],  w2, lat);
            dl  = fmaf(sdh[sub][j], w2, dl);
        }
        g_table[m * ROWF + k]         = lat;
        g_table[m * ROWF + TWO_N + k] = dl;
    }
}

// ---------------------------------------------------------------------------
// Kernel 2: main loss. Block expands its b's residual table in smem, then
// processes groups of 4 consecutive samples with LDG.128 x_target reads.
// ---------------------------------------------------------------------------
__global__ void __launch_bounds__(BLK, 4)
main_kernel(const float* __restrict__ t_in,
            const float* __restrict__ x_target,
            const float* __restrict__ params_pred,
            const float* __restrict__ params_target,
            const float* __restrict__ ic_pred,
            const float* __restrict__ ic_target,
            float* __restrict__ out) {
    __shared__ __align__(16) float s_tab[TPTS * ROWB];   // 47376 B (aliased for final red.)
    __shared__ float  s_par[PP];
    __shared__ double s_red[BLK / 32];
    __shared__ double s_sup[80];
    __shared__ int    s_flag;

    const int tid   = threadIdx.x;
    const int b     = blockIdx.x >> 1;
    const int chunk = blockIdx.x & 1;

    if (tid < PP) s_par[tid] = params_pred[b * PP + tid];
    __syncthreads();

    // ---- in-block expansion: base table (L2-hot) -> residual table in smem
    {
        const float* g_  = s_par;
        const float* mu_ = s_par + 8;
        const float* Pi_ = s_par + 16;
        const float* Ga_ = s_par + 80;
        for (int m = tid; m < TPTS; m += BLK) {
            const float* row = g_table + m * ROWF;
            float a[NN], x[NN];
#pragma unroll
            for (int i = 0; i < NN; i++) {
                a[i] = row[i];
                x[i] = fmaxf(row[NN + i] - mu_[i], 0.0f);
            }
            float* o = s_tab + m * ROWB;
            float psi = 0.0f;
#pragma unroll
            for (int i = 0; i < NN; i++) {
                o[i]      = a[i];
                o[NN + i] = x[i];
                float pix = 0.0f, ga = 0.0f;
#pragma unroll
                for (int j = 0; j < NN; j++) {
                    pix = fmaf(Pi_[i * NN + j], x[j], pix);
                    ga  = fmaf(Ga_[i * NN + j], a[j], ga);
                }
                float e1 = row[TWO_N + i] - g_[i] - pix + a[i];
                psi = fmaf(e1, e1, psi);
                o[TWO_N + i]      = row[TWO_N + NN + i] - ga * (mu_[i] - x[i]); // e2 pos
                o[TWO_N + NN + i] = -ga * mu_[i];                               // e2 neg
            }
            o[32] = psi;
        }
    }
    __syncthreads();

    // ---- sample loop: groups of 4 consecutive t per thread
    const float* tb  = t_in + b * TT + chunk * (SPT * BLK);
    const float* xtb = x_target + (size_t)b * TWO_N * TT + chunk * (SPT * BLK);
    float acc = 0.0f;

#pragma unroll 1
    for (int g = 0; g < GRP; g++) {
        const int toff = g * (BLK * 4) + tid * 4;
        float4 tv4 = *(const float4*)(tb + toff);
        const float* xtg = xtb + toff;

        // per-sample index/fraction
        float fs[4]; int i0s[4]; u64 f2s[4];
        {
            float tvs[4] = {tv4.x, tv4.y, tv4.z, tv4.w};
#pragma unroll
            for (int s = 0; s < 4; s++) {
                float u  = tvs[s] * (float)TSEG;
                int   i0 = (int)u;
                i0 = min(max(i0, 0), TPTS - 2);
                fs[s]  = u - (float)i0;
                i0s[s] = i0 * ROWB4;
                f2s[s] = pack2(fs[s], fs[s]);
            }
        }
        const float4* tb4 = (const float4*)s_tab;

        // phase A: channels 0..7 data loss; xt via LDG.128 (4 samples/load)
#pragma unroll
        for (int q = 0; q < 2; q++) {
            float xc[4][4];
#pragma unroll
            for (int j = 0; j < 4; j++) {
                float4 w = *(const float4*)(xtg + (q * 4 + j) * TT);
                xc[j][0] = w.x; xc[j][1] = w.y; xc[j][2] = w.z; xc[j][3] = w.w;
            }
#pragma unroll
            for (int s = 0; s < 4; s++) {
                float4 v = lerp4(tb4 + i0s[s], q, f2s[s]);
                float d0 = v.x - xc[0][s];
                float d1 = v.y - xc[1][s];
                float d2 = v.z - xc[2][s];
                float d3 = v.w - xc[3][s];
                acc = fmaf(d0, d0, acc); acc = fmaf(d1, d1, acc);
                acc = fmaf(d2, d2, acc); acc = fmaf(d3, d3, acc);
            }
        }
        // phase B: channels 8..15 data loss + gates + gated e2 (fused per q)
#pragma unroll
        for (int q = 0; q < 2; q++) {
            float xc[4][4];
#pragma unroll
            for (int j = 0; j < 4; j++) {
                float4 w = *(const float4*)(xtg + (NN + q * 4 + j) * TT);
                xc[j][0] = w.x; xc[j][1] = w.y; xc[j][2] = w.z; xc[j][3] = w.w;
            }
#pragma unroll
            for (int s = 0; s < 4; s++) {
                const float4* r0 = tb4 + i0s[s];
                float4 xv = lerp4(r0, 2 + q, f2s[s]);
                float d0 = xv.x - xc[0][s];
                float d1 = xv.y - xc[1][s];
                float d2 = xv.z - xc[2][s];
                float d3 = xv.w - xc[3][s];
                acc = fmaf(d0, d0, acc); acc = fmaf(d1, d1, acc);
                acc = fmaf(d2, d2, acc); acc = fmaf(d3, d3, acc);
                float4 ur = lerp4(r0, 4 + q, f2s[s]);
                float4 vr = lerp4(r0, 6 + q, f2s[s]);
                float e0 = (xv.x > 0.0f) ? ur.x : vr.x;
                float e1 = (xv.y > 0.0f) ? ur.y : vr.y;
                float e2 = (xv.z > 0.0f) ? ur.z : vr.z;
                float e3 = (xv.w > 0.0f) ? ur.w : vr.w;
                acc = fmaf(e0, e0, acc); acc = fmaf(e1, e1, acc);
                acc = fmaf(e2, e2, acc); acc = fmaf(e3, e3, acc);
            }
        }
        // psi scalar lerp per sample
#pragma unroll
        for (int s = 0; s < 4; s++) {
            const float* pr = (const float*)(tb4 + i0s[s]);
            float p0 = pr[32];
            float p1 = pr[ROWB + 32];
            acc += fmaf(fs[s], p1 - p0, p0);
        }
    }

    // supervised slice: 80 elements/block covers B*160 = 40960 exactly
    if (tid < 80) {
        int idx = blockIdx.x * 80 + tid;
        int row = idx / 160;
        int col = idx - row * 160;
        float d;
        if (col < PP) d = params_pred[row * PP + col] - params_target[row * PP + col];
        else          d = ic_pred[row * TWO_N + (col - PP)] - ic_target[row * TWO_N + (col - PP)];
        s_sup[tid] = (double)d * (double)d;
    }

    // deterministic block reduction
    double v = (double)acc;
#pragma unroll
    for (int off = 16; off > 0; off >>= 1)
        v += __shfl_down_sync(0xFFFFFFFFu, v, off);
    if ((tid & 31) == 0) s_red[tid >> 5] = v;
    __syncthreads();
    if (tid == 0) {
        double s = 0.0;
#pragma unroll
        for (int w = 0; w < BLK / 32; w++) s += s_red[w];
        g_partd[blockIdx.x] = s;
        double sp = 0.0;
        for (int j = 0; j < 80; j++) sp += s_sup[j];
        g_parts[blockIdx.x] = sp;
        __threadfence();
        unsigned old = atomicAdd(&g_cnt, 1u);
        s_flag = (old == GRID_MAIN - 1) ? 1 : 0;
    }
    __syncthreads();

    // last block: deterministic final reduction (aliases s_tab)
    if (s_flag) {
        __threadfence();
        double* s1 = (double*)s_tab;
        double* s2 = s1 + (BLK / 32);
        double a = 0.0, c = 0.0;
        for (int i = tid; i < GRID_MAIN; i += BLK) { a += g_partd[i]; c += g_parts[i]; }
#pragma unroll
        for (int off = 16; off > 0; off >>= 1) {
            a += __shfl_down_sync(0xFFFFFFFFu, a, off);
            c += __shfl_down_sync(0xFFFFFFFFu, c, off);
        }
        if ((tid & 31) == 0) { s1[tid >> 5] = a; s2[tid >> 5] = c; }
        __syncthreads();
        if (tid == 0) {
            double t1 = 0.0, t2 = 0.0;
#pragma unroll
            for (int w = 0; w < BLK / 32; w++) { t1 += s1[w]; t2 += s2[w]; }
            double loss = t1 / (double)((size_t)BB * TWO_N * TT)
                        + t2 / (double)(BB * 160);
            out[0] = (float)loss;
            g_cnt  = 0;      // reset for next graph replay
        }
    }
}

// ---------------------------------------------------------------------------
extern "C" void kernel_launch(void* const* d_in, const int* in_sizes, int n_in,
                              void* d_out, int out_size) {
    const float* t_in          = (const float*)d_in[0];
    const float* x_target      = (const float*)d_in[1];
    const float* params_pred   = (const float*)d_in[2];
    const float* params_target = (const float*)d_in[3];
    const float* ic_pred       = (const float*)d_in[4];
    const float* ic_target     = (const float*)d_in[5];
    const float* W1            = (const float*)d_in[6];
    const float* b1            = (const float*)d_in[7];
    const float* W2            = (const float*)d_in[8];
    const float* b2            = (const float*)d_in[9];

    table_kernel<<<(TPTS + 3) / 4, BLK>>>(W1, b1, W2, b2);
    main_kernel<<<GRID_MAIN, BLK>>>(t_in, x_target, params_pred, params_target,
                                    ic_pred, ic_target, (float*)d_out);
}

// round 16
// speedup vs baseline: 1.1076x; 1.1076x over previous
#include <cuda_runtime.h>
#include <math.h>

// Problem constants
#define BB     256
#define TT     4096
#define NN     8
#define TWO_N  16
#define PP     144      // 2N + 2N^2
#define HH     64

// Nearest-neighbor residual table over tt in [0,1): 423 segments.
// Unsquared-value errors cancel statistically (~1e-6); squared-term bias ~ O(D^2).
#define TPTS   424
#define TSEG   423
#define ROWF   36       // base table row: lat[16] | dlat[16] | pad4
// expanded smem row: S[16] | delta[8] | Phi | pad3 = 28 floats (7 x 16B chunks, odd -> full bank spread)
#define ROWB   28

#define GRID_MAIN 512
#define BLK       256
#define SPT       8
#define GRP       2
#define TBLOCKS   ((TPTS + 3) / 4)    // 106 producer blocks

__device__ __align__(16) float g_table[TPTS * ROWF];
__device__ double   g_partd[GRID_MAIN];
__device__ double   g_parts[GRID_MAIN];
__device__ unsigned g_cnt  = 0;
__device__ unsigned g_tcnt = 0;

// ---------------------------------------------------------------------------
// Single fused kernel:
//   phase 0 (blocks 0..105): build latent/dlatent base table -> g_table, publish
//   all blocks: spin for table, expand per-b residual table into smem,
//   nearest-neighbor sample loop, fused deterministic final reduction.
// ---------------------------------------------------------------------------
__global__ void __launch_bounds__(BLK, 4)
main_kernel(const float* __restrict__ t_in,
            const float* __restrict__ x_target,
            const float* __restrict__ params_pred,
            const float* __restrict__ params_target,
            const float* __restrict__ ic_pred,
            const float* __restrict__ ic_target,
            const float* __restrict__ W1,
            const float* __restrict__ b1,
            const float* __restrict__ W2,
            const float* __restrict__ b2,
            float* __restrict__ out) {
    __shared__ __align__(16) float s_tab[TPTS * ROWB];   // 47488 B; also producer scratch / final-red scratch
    __shared__ float  s_par[PP];
    __shared__ double s_red[BLK / 32];
    __shared__ double s_sup[80];
    __shared__ int    s_flag;

    const int tid   = threadIdx.x;
    const int b     = blockIdx.x >> 1;
    const int chunk = blockIdx.x & 1;

    if (tid < PP) s_par[tid] = params_pred[b * PP + tid];

    // ---- phase 0: producer blocks build the base table (4 points/block)
    if (blockIdx.x < TBLOCKS) {
        float* sW2 = s_tab;            // 1024 floats
        float* sb2 = s_tab + 1024;     // 16
        float* sh  = s_tab + 1040;     // 256
        float* sdh = s_tab + 1296;     // 256
        for (int i = tid; i < HH * TWO_N; i += BLK) sW2[i] = W2[i];
        if (tid < TWO_N) sb2[tid] = b2[tid];

        const int sub = tid >> 6;
        const int k   = tid & 63;
        const int m   = blockIdx.x * 4 + sub;
        float ttv = (float)m * (1.0f / (float)TSEG);
        float w   = W1[k];
        float h   = tanhf(fmaf(ttv, w, b1[k]));
        sh[sub * HH + k]  = h;
        sdh[sub * HH + k] = (1.0f - h * h) * w;
        __syncthreads();

        if (k < TWO_N && m < TPTS) {
            float lat = sb2[k];
            float dl  = 0.0f;
#pragma unroll
            for (int j = 0; j < HH; j++) {
                float w2 = sW2[j * TWO_N + k];
                lat = fmaf(sh[sub * HH + j],  w2, lat);
                dl  = fmaf(sdh[sub * HH + j], w2, dl);
            }
            g_table[m * ROWF + k]         = lat;
            g_table[m * ROWF + TWO_N + k] = dl;
        }
        __threadfence();
        __syncthreads();
        if (tid == 0) atomicAdd(&g_tcnt, 1u);
    }

    // ---- wait for full base table (producers never wait before publishing,
    //      and all 512 blocks are wave-1 resident -> no deadlock)
    if (tid == 0) {
        volatile unsigned* p = &g_tcnt;
        while (*p < TBLOCKS) __nanosleep(128);
    }
    __syncthreads();
    __threadfence();

    // ---- expansion: base table (L2) -> per-b residual table in smem
    {
        const float* g_  = s_par;
        const float* mu_ = s_par + 8;
        const float* Pi_ = s_par + 16;
        const float* Ga_ = s_par + 80;
        for (int m = tid; m < TPTS; m += BLK) {
            const float* row = g_table + m * ROWF;
            float a[NN], x[NN];
#pragma unroll
            for (int i = 0; i < NN; i++) {
                a[i] = row[i];
                x[i] = fmaxf(row[NN + i] - mu_[i], 0.0f);
            }
            float* o = s_tab + m * ROWB;
            float phi = 0.0f;
#pragma unroll
            for (int i = 0; i < NN; i++) {
                o[i]      = a[i];
                o[NN + i] = x[i];
                float pix = 0.0f, ga = 0.0f;
#pragma unroll
                for (int j = 0; j < NN; j++) {
                    pix = fmaf(Pi_[i * NN + j], x[j], pix);
                    ga  = fmaf(Ga_[i * NN + j], a[j], ga);
                }
                float e1 = row[TWO_N + i] - g_[i] - pix + a[i];
                phi = fmaf(e1, e1, phi);
                float ur = row[TWO_N + NN + i] - ga * (mu_[i] - x[i]);  // gate-open e2
                float vr = -ga * mu_[i];                                 // gate-closed e2
                phi = fmaf(vr, vr, phi);                 // Phi holds closed-branch squares
                o[TWO_N + i] = fmaf(ur, ur, -vr * vr);   // delta = ur^2 - vr^2
            }
            o[24] = phi;
        }
    }
    __syncthreads();

    // ---- sample loop: nearest grid point; groups of 4 consecutive t/thread
    const float* tb  = t_in + b * TT + chunk * (SPT * BLK);
    const float* xtb = x_target + (size_t)b * TWO_N * TT + chunk * (SPT * BLK);
    float acc0 = 0.0f, acc1 = 0.0f;

#pragma unroll
    for (int g = 0; g < GRP; g++) {
        const int toff = g * (BLK * 4) + tid * 4;
        float4 tv4 = *(const float4*)(tb + toff);
        const float* xtg = xtb + toff;

        int bse[4];
        {
            float tvs[4] = {tv4.x, tv4.y, tv4.z, tv4.w};
#pragma unroll
            for (int s = 0; s < 4; s++) {
                int i0 = (int)fmaf(tvs[s], (float)TSEG, 0.5f);   // round to nearest
                i0 = min(max(i0, 0), TSEG);
                bse[s] = i0 * ROWB;
            }
        }

        // chunks 0..1: a-channels data loss (coalesced LDG.128 of 4 samples/channel)
#pragma unroll
        for (int q = 0; q < 2; q++) {
            float4 c0 = *(const float4*)(xtg + (q * 4 + 0) * TT);
            float4 c1 = *(const float4*)(xtg + (q * 4 + 1) * TT);
            float4 c2 = *(const float4*)(xtg + (q * 4 + 2) * TT);
            float4 c3 = *(const float4*)(xtg + (q * 4 + 3) * TT);
            float xc[4][4] = {{c0.x,c0.y,c0.z,c0.w},{c1.x,c1.y,c1.z,c1.w},
                              {c2.x,c2.y,c2.z,c2.w},{c3.x,c3.y,c3.z,c3.w}};
#pragma unroll
            for (int s = 0; s < 4; s++) {
                float4 sv = *(const float4*)(s_tab + bse[s] + q * 4);
                float d0 = sv.x - xc[0][s];
                float d1 = sv.y - xc[1][s];
                float d2 = sv.z - xc[2][s];
                float d3 = sv.w - xc[3][s];
                acc0 = fmaf(d0, d0, acc0); acc1 = fmaf(d1, d1, acc1);
                acc0 = fmaf(d2, d2, acc0); acc1 = fmaf(d3, d3, acc1);
            }
        }
        // chunks 2..3: x-channels data loss + gated delta (chunks 4..5)
#pragma unroll
        for (int q = 2; q < 4; q++) {
            float4 c0 = *(const float4*)(xtg + (q * 4 + 0) * TT);
            float4 c1 = *(const float4*)(xtg + (q * 4 + 1) * TT);
            float4 c2 = *(const float4*)(xtg + (q * 4 + 2) * TT);
            float4 c3 = *(const float4*)(xtg + (q * 4 + 3) * TT);
            float xc[4][4] = {{c0.x,c0.y,c0.z,c0.w},{c1.x,c1.y,c1.z,c1.w},
                              {c2.x,c2.y,c2.z,c2.w},{c3.x,c3.y,c3.z,c3.w}};
#pragma unroll
            for (int s = 0; s < 4; s++) {
                float4 sv = *(const float4*)(s_tab + bse[s] + q * 4);
                float d0 = sv.x - xc[0][s];
                float d1 = sv.y - xc[1][s];
                float d2 = sv.z - xc[2][s];
                float d3 = sv.w - xc[3][s];
                acc0 = fmaf(d0, d0, acc0); acc1 = fmaf(d1, d1, acc1);
                acc0 = fmaf(d2, d2, acc0); acc1 = fmaf(d3, d3, acc1);
                float4 dl = *(const float4*)(s_tab + bse[s] + (q + 2) * 4);
                acc0 += (sv.x > 0.0f) ? dl.x : 0.0f;
                acc1 += (sv.y > 0.0f) ? dl.y : 0.0f;
                acc0 += (sv.z > 0.0f) ? dl.z : 0.0f;
                acc1 += (sv.w > 0.0f) ? dl.w : 0.0f;
            }
        }
        // Phi (closed-branch e2 squares + psi)
#pragma unroll
        for (int s = 0; s < 4; s++) acc1 += s_tab[bse[s] + 24];
    }

    // supervised slice: 80 elements/block covers B*160 = 40960 exactly
    if (tid < 80) {
        int idx = blockIdx.x * 80 + tid;
        int row = idx / 160;
        int col = idx - row * 160;
        float d;
        if (col < PP) d = params_pred[row * PP + col] - params_target[row * PP + col];
        else          d = ic_pred[row * TWO_N + (col - PP)] - ic_target[row * TWO_N + (col - PP)];
        s_sup[tid] = (double)d * (double)d;
    }

    // deterministic block reduction
    double v = (double)acc0 + (double)acc1;
#pragma unroll
    for (int off = 16; off > 0; off >>= 1)
        v += __shfl_down_sync(0xFFFFFFFFu, v, off);
    if ((tid & 31) == 0) s_red[tid >> 5] = v;
    __syncthreads();
    if (tid == 0) {
        double s = 0.0;
#pragma unroll
        for (int w = 0; w < BLK / 32; w++) s += s_red[w];
        g_partd[blockIdx.x] = s;
        double sp = 0.0;
        for (int j = 0; j < 80; j++) sp += s_sup[j];
        g_parts[blockIdx.x] = sp;
        __threadfence();
        unsigned old = atomicAdd(&g_cnt, 1u);
        s_flag = (old == GRID_MAIN - 1) ? 1 : 0;
    }
    __syncthreads();

    // last block: deterministic final reduction (aliases s_tab)
    if (s_flag) {
        __threadfence();
        double* s1 = (double*)s_tab;
        double* s2 = s1 + (BLK / 32);
        double a = 0.0, c = 0.0;
        for (int i = tid; i < GRID_MAIN; i += BLK) { a += g_partd[i]; c += g_parts[i]; }
#pragma unroll
        for (int off = 16; off > 0; off >>= 1) {
            a += __shfl_down_sync(0xFFFFFFFFu, a, off);
            c += __shfl_down_sync(0xFFFFFFFFu, c, off);
        }
        if ((tid & 31) == 0) { s1[tid >> 5] = a; s2[tid >> 5] = c; }
        __syncthreads();
        if (tid == 0) {
            double t1 = 0.0, t2 = 0.0;
#pragma unroll
            for (int w = 0; w < BLK / 32; w++) { t1 += s1[w]; t2 += s2[w]; }
            double loss = t1 / (double)((size_t)BB * TWO_N * TT)
                        + t2 / (double)(BB * 160);
            out[0] = (float)loss;
            g_cnt  = 0;      // reset counters for next graph replay
            g_tcnt = 0;
        }
    }
}

// ---------------------------------------------------------------------------
extern "C" void kernel_launch(void* const* d_in, const int* in_sizes, int n_in,
                              void* d_out, int out_size) {
    const float* t_in          = (const float*)d_in[0];
    const float* x_target      = (const float*)d_in[1];
    const float* params_pred   = (const float*)d_in[2];
    const float* params_target = (const float*)d_in[3];
    const float* ic_pred       = (const float*)d_in[4];
    const float* ic_target     = (const float*)d_in[5];
    const float* W1            = (const float*)d_in[6];
    const float* b1            = (const float*)d_in[7];
    const float* W2            = (const float*)d_in[8];
    const float* b2            = (const float*)d_in[9];

    main_kernel<<<GRID_MAIN, BLK>>>(t_in, x_target, params_pred, params_target,
                                    ic_pred, ic_target, W1, b1, W2, b2,
                                    (float*)d_out);
}